// round 4
// baseline (speedup 1.0000x reference)
#include <cuda_runtime.h>
#include <cstdint>
#include <cstddef>

// ============================ problem constants ============================
#define BATCH 16
#define SEQ   2048
#define DIMD  64
#define QT    128          // q rows per CTA
#define KT    128          // kv rows per tile
#define NKT   (SEQ / KT)   // 16
#define PITCH 68           // smem row pitch in floats (bank-conflict-free)
#define TILEF (128 * PITCH)        // floats per tile buffer (8704)
#define TILEB (TILEF * 4)          // bytes per tile buffer (34816)

// smem: kbuf[2], vbuf[2], rowsums
#define SM_FLOATS (4 * TILEF + 128)
#define SM_BYTES  (SM_FLOATS * 4)  // 139,776 bytes

// ============================ helpers ============================
__device__ __forceinline__ uint32_t f2t(float f) {
    uint32_t u;
    asm("cvt.rna.tf32.f32 %0, %1;" : "=r"(u) : "f"(f));
    return u;
}
__device__ __forceinline__ float tof(uint32_t u) { return __uint_as_float(u); }

__device__ __forceinline__ uint32_t smem_u32(const void* p) {
    uint32_t a;
    asm("{ .reg .u64 t; cvta.to.shared.u64 t, %1; cvt.u32.u64 %0, t; }" : "=r"(a) : "l"(p));
    return a;
}
__device__ __forceinline__ void cpasync16(uint32_t dst, const float* src) {
    asm volatile("cp.async.cg.shared.global [%0], [%1], 16;" :: "r"(dst), "l"(src));
}
#define CP_COMMIT() asm volatile("cp.async.commit_group;" ::: "memory")
#define CP_WAIT0()  asm volatile("cp.async.wait_group 0;" ::: "memory")

__device__ __forceinline__ void mma8(float& c0, float& c1, float& c2, float& c3,
                                     uint32_t a0, uint32_t a1, uint32_t a2, uint32_t a3,
                                     uint32_t b0, uint32_t b1) {
    asm volatile(
        "mma.sync.aligned.m16n8k8.row.col.f32.tf32.tf32.f32 "
        "{%0,%1,%2,%3},{%4,%5,%6,%7},{%8,%9},{%0,%1,%2,%3};"
        : "+f"(c0), "+f"(c1), "+f"(c2), "+f"(c3)
        : "r"(a0), "r"(a1), "r"(a2), "r"(a3), "r"(b0), "r"(b1));
}

// stage one 128x64 f32 tile (raw bits) into smem at pitch 272B via cp.async
__device__ __forceinline__ void ld_tile(uint32_t dst, const float* __restrict__ g, int tid) {
#pragma unroll
    for (int i = 0; i < 8; i++) {
        int idx = tid + i * 256;           // 2048 16B-chunks: 128 rows x 16
        int row = idx >> 4, c4 = idx & 15;
        cpasync16(dst + row * (PITCH * 4) + c4 * 16, g + row * DIMD + c4 * 4);
    }
}

// ============================ fused attention ============================
__global__ void __launch_bounds__(256, 1)
attn_kernel(const float* __restrict__ Q, const float* __restrict__ K,
            const float* __restrict__ V, float* __restrict__ ctx_out,
            float* __restrict__ attn_out, int has_attn)
{
    extern __shared__ float sm[];
    float* kbuf[2] = { sm,             sm + TILEF };
    float* vbuf[2] = { sm + 2 * TILEF, sm + 3 * TILEF };
    float* rs      = sm + 4 * TILEF;
    const uint32_t smb = smem_u32(sm);
    const uint32_t kd[2] = { smb,             smb + TILEB };
    const uint32_t vd[2] = { smb + 2 * TILEB, smb + 3 * TILEB };

    const int tid  = threadIdx.x;
    const int w    = tid >> 5;
    const int lane = tid & 31;
    const int r    = lane >> 2;   // 0..7
    const int c    = lane & 3;    // 0..3

    const int b  = blockIdx.x >> 4;
    const int q0 = (blockIdx.x & 15) << 7;
    const int qr = q0 + 16 * w + r;           // this lane's first q row

    const float* Kb = K + (size_t)b * SEQ * DIMD;
    const float* Vb = V + (size_t)b * SEQ * DIMD;

    // ---- Q fragments (exact 2xTF32 split), persistent in registers ----
    uint32_t qh[32], ql[32];
    {
        const float* q0p = Q + ((size_t)b * SEQ + qr) * DIMD;
        const float* q1p = q0p + 8 * DIMD;
#pragma unroll
        for (int j = 0; j < 8; j++) {
            float f;
            f = q0p[8 * j + c]     * 0.125f; qh[4*j+0] = f2t(f); ql[4*j+0] = f2t(f - tof(qh[4*j+0]));
            f = q1p[8 * j + c]     * 0.125f; qh[4*j+1] = f2t(f); ql[4*j+1] = f2t(f - tof(qh[4*j+1]));
            f = q0p[8 * j + c + 4] * 0.125f; qh[4*j+2] = f2t(f); ql[4*j+2] = f2t(f - tof(qh[4*j+2]));
            f = q1p[8 * j + c + 4] * 0.125f; qh[4*j+3] = f2t(f); ql[4*j+3] = f2t(f - tof(qh[4*j+3]));
        }
    }

    // =================== PASS A: rowsums of exp(scores) ===================
    float rs0 = 0.f, rs1 = 0.f;
    ld_tile(kd[0], Kb, tid);
    CP_COMMIT();
    for (int t = 0; t < NKT; t++) {
        CP_WAIT0();
        __syncthreads();
        if (t + 1 < NKT) {
            ld_tile(kd[(t + 1) & 1], Kb + (size_t)(t + 1) * KT * DIMD, tid);
            CP_COMMIT();
        }
        const float* kh = kbuf[t & 1];
#pragma unroll 4
        for (int nb = 0; nb < 16; nb++) {
            // two independent accumulator chains (even/odd j)
            float e0 = 0.f, e1 = 0.f, e2 = 0.f, e3 = 0.f;
            float o0 = 0.f, o1 = 0.f, o2 = 0.f, o3 = 0.f;
            const int base = (nb * 8 + r) * PITCH + c;
#pragma unroll
            for (int j2 = 0; j2 < 4; j2++) {
                const int je = 2 * j2, jo = 2 * j2 + 1;
                uint32_t be0 = __float_as_uint(kh[base + 8 * je]);
                uint32_t be1 = __float_as_uint(kh[base + 8 * je + 4]);
                uint32_t bo0 = __float_as_uint(kh[base + 8 * jo]);
                uint32_t bo1 = __float_as_uint(kh[base + 8 * jo + 4]);
                mma8(e0, e1, e2, e3, qh[4*je], qh[4*je+1], qh[4*je+2], qh[4*je+3], be0, be1);
                mma8(o0, o1, o2, o3, qh[4*jo], qh[4*jo+1], qh[4*jo+2], qh[4*jo+3], bo0, bo1);
            }
            rs0 += __expf(e0 + o0) + __expf(e1 + o1);
            rs1 += __expf(e2 + o2) + __expf(e3 + o3);
        }
    }
    // prefetch pass-B tile 0 (K+V) while we reduce rowsums
    ld_tile(kd[0], Kb, tid);
    ld_tile(vd[0], Vb, tid);
    CP_COMMIT();

    rs0 += __shfl_xor_sync(0xFFFFFFFFu, rs0, 1);
    rs0 += __shfl_xor_sync(0xFFFFFFFFu, rs0, 2);
    rs1 += __shfl_xor_sync(0xFFFFFFFFu, rs1, 1);
    rs1 += __shfl_xor_sync(0xFFFFFFFFu, rs1, 2);
    __syncthreads();   // all warps done reading kbuf (pass A) before reuse
    if (c == 0) { rs[16 * w + r] = rs0; rs[16 * w + r + 8] = rs1; }
    __syncthreads();
    const float inv0 = 1.0f / rs[16 * w + r];
    const float inv1 = 1.0f / rs[16 * w + r + 8];

    // =================== PASS B: attn + context ===================
    float cx[32];
#pragma unroll
    for (int i = 0; i < 32; i++) cx[i] = 0.f;

    for (int t = 0; t < NKT; t++) {
        CP_WAIT0();
        __syncthreads();
        if (t + 1 < NKT) {
            ld_tile(kd[(t + 1) & 1], Kb + (size_t)(t + 1) * KT * DIMD, tid);
            ld_tile(vd[(t + 1) & 1], Vb + (size_t)(t + 1) * KT * DIMD, tid);
            CP_COMMIT();
        }
        const float* kh = kbuf[t & 1];
        const float* vv = vbuf[t & 1];

        float* a0p = attn_out + ((size_t)b * SEQ + qr) * SEQ + t * KT;
        float* a1p = a0p + (size_t)8 * SEQ;

#pragma unroll 2
        for (int nb = 0; nb < 16; nb++) {
            // four independent accumulator chains: (qh,ql) x (even j, odd j)
            float h0 = 0.f, h1 = 0.f, h2 = 0.f, h3 = 0.f;
            float g0 = 0.f, g1 = 0.f, g2 = 0.f, g3 = 0.f;
            float l0 = 0.f, l1 = 0.f, l2 = 0.f, l3 = 0.f;
            float m0 = 0.f, m1 = 0.f, m2 = 0.f, m3 = 0.f;
            const int base = (nb * 8 + r) * PITCH + c;
#pragma unroll
            for (int j2 = 0; j2 < 4; j2++) {
                const int je = 2 * j2, jo = 2 * j2 + 1;
                // RN-round K fragments (kills truncation bias/tails)
                uint32_t be0 = f2t(kh[base + 8 * je]);
                uint32_t be1 = f2t(kh[base + 8 * je + 4]);
                uint32_t bo0 = f2t(kh[base + 8 * jo]);
                uint32_t bo1 = f2t(kh[base + 8 * jo + 4]);
                mma8(h0, h1, h2, h3, qh[4*je], qh[4*je+1], qh[4*je+2], qh[4*je+3], be0, be1);
                mma8(g0, g1, g2, g3, qh[4*jo], qh[4*jo+1], qh[4*jo+2], qh[4*jo+3], bo0, bo1);
                mma8(l0, l1, l2, l3, ql[4*je], ql[4*je+1], ql[4*je+2], ql[4*je+3], be0, be1);
                mma8(m0, m1, m2, m3, ql[4*jo], ql[4*jo+1], ql[4*jo+2], ql[4*jo+3], bo0, bo1);
            }
            float p0 = __expf((h0 + g0) + (l0 + m0)) * inv0;
            float p1 = __expf((h1 + g1) + (l1 + m1)) * inv0;
            float p2 = __expf((h2 + g2) + (l2 + m2)) * inv1;
            float p3 = __expf((h3 + g3) + (l3 + m3)) * inv1;

            if (has_attn) {
                *(float2*)(a0p + nb * 8 + 2 * c) = make_float2(p0, p1);
                *(float2*)(a1p + nb * 8 + 2 * c) = make_float2(p2, p3);
            }

            // P fragments for PV (k-permutation trick: logical k c->2c, c+4->2c+1)
            uint32_t pa0 = f2t(p0), pa1 = f2t(p2), pa2 = f2t(p1), pa3 = f2t(p3);

            const int vb2 = (nb * 8 + 2 * c) * PITCH + r;
#pragma unroll
            for (int nd = 0; nd < 8; nd++) {
                // RN-round V fragments
                uint32_t b0 = f2t(vv[vb2 + 8 * nd]);
                uint32_t b1 = f2t(vv[vb2 + PITCH + 8 * nd]);
                mma8(cx[4*nd], cx[4*nd+1], cx[4*nd+2], cx[4*nd+3], pa0, pa1, pa2, pa3, b0, b1);
            }
        }
    }

    // ---- write context ----
    float* c0p = ctx_out + ((size_t)b * SEQ + qr) * DIMD;
    float* c1p = c0p + 8 * DIMD;
#pragma unroll
    for (int nd = 0; nd < 8; nd++) {
        *(float2*)(c0p + 8 * nd + 2 * c) = make_float2(cx[4*nd],   cx[4*nd+1]);
        *(float2*)(c1p + 8 * nd + 2 * c) = make_float2(cx[4*nd+2], cx[4*nd+3]);
    }
}

// ============================ launch ============================
extern "C" void kernel_launch(void* const* d_in, const int* in_sizes, int n_in,
                              void* d_out, int out_size) {
    const float* q = (const float*)d_in[0];
    const float* k = (const float*)d_in[1];
    const float* v = (const float*)d_in[2];
    float* out = (float*)d_out;

    const long long CTX_ELEMS  = (long long)BATCH * SEQ * DIMD;   // 2,097,152
    const long long ATTN_ELEMS = (long long)BATCH * SEQ * SEQ;    // 67,108,864
    float* ctx_out  = out;
    float* attn_out = out + CTX_ELEMS;
    int has_attn = ((long long)out_size >= CTX_ELEMS + ATTN_ELEMS) ? 1 : 0;

    cudaFuncSetAttribute(attn_kernel, cudaFuncAttributeMaxDynamicSharedMemorySize, SM_BYTES);
    attn_kernel<<<BATCH * (SEQ / QT), 256, SM_BYTES>>>(q, k, v, ctx_out, attn_out, has_attn);
}

// round 5
// speedup vs baseline: 1.3427x; 1.3427x over previous
#include <cuda_runtime.h>
#include <cstdint>
#include <cstddef>

// ============================ problem constants ============================
#define BATCH 16
#define SEQ   2048
#define DIMD  64
#define QT    128          // q rows per CTA
#define KT    64           // kv rows per tile
#define NKT   (SEQ / KT)   // 32
#define NB    (KT / 8)     // 8 n-blocks per tile
#define PITCH 68           // smem row pitch in floats (bank-conflict-free)
#define TILEF (KT * PITCH)         // floats per tile buffer (4352)
#define TILEB (TILEF * 4)          // bytes per tile buffer (17408)

// smem: buf[4] (pass A: 4-deep K ring; pass B: K[2] + V[2]), rowsums
#define SM_FLOATS (4 * TILEF + 128)
#define SM_BYTES  (SM_FLOATS * 4)  // 70,144 bytes -> 2 CTAs/SM

// ============================ helpers ============================
__device__ __forceinline__ uint32_t f2t(float f) {
    uint32_t u;
    asm("cvt.rna.tf32.f32 %0, %1;" : "=r"(u) : "f"(f));
    return u;
}
__device__ __forceinline__ uint32_t smem_u32(const void* p) {
    uint32_t a;
    asm("{ .reg .u64 t; cvta.to.shared.u64 t, %1; cvt.u32.u64 %0, t; }" : "=r"(a) : "l"(p));
    return a;
}
__device__ __forceinline__ void cpasync16(uint32_t dst, const float* src) {
    asm volatile("cp.async.cg.shared.global [%0], [%1], 16;" :: "r"(dst), "l"(src));
}
#define CP_COMMIT() asm volatile("cp.async.commit_group;" ::: "memory")
#define CP_WAIT(n)  asm volatile("cp.async.wait_group %0;" :: "n"(n) : "memory")

__device__ __forceinline__ void mma8(float& c0, float& c1, float& c2, float& c3,
                                     uint32_t a0, uint32_t a1, uint32_t a2, uint32_t a3,
                                     uint32_t b0, uint32_t b1) {
    asm volatile(
        "mma.sync.aligned.m16n8k8.row.col.f32.tf32.tf32.f32 "
        "{%0,%1,%2,%3},{%4,%5,%6,%7},{%8,%9},{%0,%1,%2,%3};"
        : "+f"(c0), "+f"(c1), "+f"(c2), "+f"(c3)
        : "r"(a0), "r"(a1), "r"(a2), "r"(a3), "r"(b0), "r"(b1));
}

// stage one 64x64 f32 tile (raw bits) into smem at pitch 272B via cp.async
__device__ __forceinline__ void ld_tile(uint32_t dst, const float* __restrict__ g, int tid) {
#pragma unroll
    for (int i = 0; i < 4; i++) {
        int idx = tid + i * 256;           // 1024 16B-chunks: 64 rows x 16
        int row = idx >> 4, c4 = idx & 15;
        cpasync16(dst + row * (PITCH * 4) + c4 * 16, g + row * DIMD + c4 * 4);
    }
}

// ============================ fused attention ============================
__global__ void __launch_bounds__(256, 2)
attn_kernel(const float* __restrict__ Q, const float* __restrict__ K,
            const float* __restrict__ V, float* __restrict__ ctx_out,
            float* __restrict__ attn_out, int has_attn)
{
    extern __shared__ float sm[];
    float* buf[4] = { sm, sm + TILEF, sm + 2 * TILEF, sm + 3 * TILEF };
    float* rs     = sm + 4 * TILEF;
    const uint32_t smb = smem_u32(sm);
    const uint32_t bd[4] = { smb, smb + TILEB, smb + 2 * TILEB, smb + 3 * TILEB };

    const int tid  = threadIdx.x;
    const int w    = tid >> 5;
    const int lane = tid & 31;
    const int r    = lane >> 2;   // 0..7
    const int c    = lane & 3;    // 0..3

    const int b  = blockIdx.x >> 4;
    const int q0 = (blockIdx.x & 15) << 7;
    const int qr = q0 + 16 * w + r;           // this lane's first q row

    const float* Kb = K + (size_t)b * SEQ * DIMD;
    const float* Vb = V + (size_t)b * SEQ * DIMD;

    // ---- Q fragments (single tf32, RN), persistent in registers ----
    uint32_t qh[32];
    {
        const float* q0p = Q + ((size_t)b * SEQ + qr) * DIMD;
        const float* q1p = q0p + 8 * DIMD;
#pragma unroll
        for (int j = 0; j < 8; j++) {
            qh[4*j+0] = f2t(q0p[8 * j + c]     * 0.125f);
            qh[4*j+1] = f2t(q1p[8 * j + c]     * 0.125f);
            qh[4*j+2] = f2t(q0p[8 * j + c + 4] * 0.125f);
            qh[4*j+3] = f2t(q1p[8 * j + c + 4] * 0.125f);
        }
    }

    // =================== PASS A: rowsums of exp(scores) ===================
    // 4-deep cp.async K ring (raw truncated K is fine for the denominator)
    float rs0 = 0.f, rs1 = 0.f;
#pragma unroll
    for (int pre = 0; pre < 3; pre++) {
        ld_tile(bd[pre], Kb + (size_t)pre * KT * DIMD, tid);
        CP_COMMIT();
    }
    for (int t = 0; t < NKT; t++) {
        CP_WAIT(2);
        __syncthreads();
        if (t + 3 < NKT) {
            ld_tile(bd[(t + 3) & 3], Kb + (size_t)(t + 3) * KT * DIMD, tid);
            CP_COMMIT();
        }
        const float* kh = buf[t & 3];
#pragma unroll
        for (int nb = 0; nb < NB; nb++) {
            float e0 = 0.f, e1 = 0.f, e2 = 0.f, e3 = 0.f;
            float o0 = 0.f, o1 = 0.f, o2 = 0.f, o3 = 0.f;
            const int base = (nb * 8 + r) * PITCH + c;
#pragma unroll
            for (int j2 = 0; j2 < 4; j2++) {
                const int je = 2 * j2, jo = 2 * j2 + 1;
                uint32_t be0 = __float_as_uint(kh[base + 8 * je]);
                uint32_t be1 = __float_as_uint(kh[base + 8 * je + 4]);
                uint32_t bo0 = __float_as_uint(kh[base + 8 * jo]);
                uint32_t bo1 = __float_as_uint(kh[base + 8 * jo + 4]);
                mma8(e0, e1, e2, e3, qh[4*je], qh[4*je+1], qh[4*je+2], qh[4*je+3], be0, be1);
                mma8(o0, o1, o2, o3, qh[4*jo], qh[4*jo+1], qh[4*jo+2], qh[4*jo+3], bo0, bo1);
            }
            rs0 += __expf(e0 + o0) + __expf(e1 + o1);
            rs1 += __expf(e2 + o2) + __expf(e3 + o3);
        }
    }
    rs0 += __shfl_xor_sync(0xFFFFFFFFu, rs0, 1);
    rs0 += __shfl_xor_sync(0xFFFFFFFFu, rs0, 2);
    rs1 += __shfl_xor_sync(0xFFFFFFFFu, rs1, 1);
    rs1 += __shfl_xor_sync(0xFFFFFFFFu, rs1, 2);
    __syncthreads();   // pass A reads done before buffer reuse
    if (c == 0) { rs[16 * w + r] = rs0; rs[16 * w + r + 8] = rs1; }

    // prefetch pass-B tile 0 (K -> buf0, V -> buf2)
    ld_tile(bd[0], Kb, tid);
    ld_tile(bd[2], Vb, tid);
    CP_COMMIT();
    __syncthreads();
    const float inv0 = 1.0f / rs[16 * w + r];
    const float inv1 = 1.0f / rs[16 * w + r + 8];

    // =================== PASS B: attn + context ===================
    float cx[32];
#pragma unroll
    for (int i = 0; i < 32; i++) cx[i] = 0.f;

    for (int t = 0; t < NKT; t++) {
        CP_WAIT(0);
        __syncthreads();
        if (t + 1 < NKT) {
            ld_tile(bd[(t + 1) & 1],       Kb + (size_t)(t + 1) * KT * DIMD, tid);
            ld_tile(bd[2 + ((t + 1) & 1)], Vb + (size_t)(t + 1) * KT * DIMD, tid);
            CP_COMMIT();
        }
        const float* kh = buf[t & 1];
        const float* vv = buf[2 + (t & 1)];

        float* a0p = attn_out + ((size_t)b * SEQ + qr) * SEQ + t * KT;
        float* a1p = a0p + (size_t)8 * SEQ;

#pragma unroll 2
        for (int nb = 0; nb < NB; nb++) {
            float e0 = 0.f, e1 = 0.f, e2 = 0.f, e3 = 0.f;
            float o0 = 0.f, o1 = 0.f, o2 = 0.f, o3 = 0.f;
            const int base = (nb * 8 + r) * PITCH + c;
#pragma unroll
            for (int j2 = 0; j2 < 4; j2++) {
                const int je = 2 * j2, jo = 2 * j2 + 1;
                // RN-round K fragments (numerator path needs RN quality)
                uint32_t be0 = f2t(kh[base + 8 * je]);
                uint32_t be1 = f2t(kh[base + 8 * je + 4]);
                uint32_t bo0 = f2t(kh[base + 8 * jo]);
                uint32_t bo1 = f2t(kh[base + 8 * jo + 4]);
                mma8(e0, e1, e2, e3, qh[4*je], qh[4*je+1], qh[4*je+2], qh[4*je+3], be0, be1);
                mma8(o0, o1, o2, o3, qh[4*jo], qh[4*jo+1], qh[4*jo+2], qh[4*jo+3], bo0, bo1);
            }
            float p0 = __expf(e0 + o0) * inv0;
            float p1 = __expf(e1 + o1) * inv0;
            float p2 = __expf(e2 + o2) * inv1;
            float p3 = __expf(e3 + o3) * inv1;

            if (has_attn) {
                *(float2*)(a0p + nb * 8 + 2 * c) = make_float2(p0, p1);
                *(float2*)(a1p + nb * 8 + 2 * c) = make_float2(p2, p3);
            }

            // P fragments for PV (k-permutation trick: logical k c->2c, c+4->2c+1)
            uint32_t pa0 = f2t(p0), pa1 = f2t(p2), pa2 = f2t(p1), pa3 = f2t(p3);

            const int vb2 = (nb * 8 + 2 * c) * PITCH + r;
#pragma unroll
            for (int nd = 0; nd < 8; nd++) {
                // RN-round V fragments
                uint32_t b0 = f2t(vv[vb2 + 8 * nd]);
                uint32_t b1 = f2t(vv[vb2 + PITCH + 8 * nd]);
                mma8(cx[4*nd], cx[4*nd+1], cx[4*nd+2], cx[4*nd+3], pa0, pa1, pa2, pa3, b0, b1);
            }
        }
    }

    // ---- write context ----
    float* c0p = ctx_out + ((size_t)b * SEQ + qr) * DIMD;
    float* c1p = c0p + 8 * DIMD;
#pragma unroll
    for (int nd = 0; nd < 8; nd++) {
        *(float2*)(c0p + 8 * nd + 2 * c) = make_float2(cx[4*nd],   cx[4*nd+1]);
        *(float2*)(c1p + 8 * nd + 2 * c) = make_float2(cx[4*nd+2], cx[4*nd+3]);
    }
}

// ============================ launch ============================
extern "C" void kernel_launch(void* const* d_in, const int* in_sizes, int n_in,
                              void* d_out, int out_size) {
    const float* q = (const float*)d_in[0];
    const float* k = (const float*)d_in[1];
    const float* v = (const float*)d_in[2];
    float* out = (float*)d_out;

    const long long CTX_ELEMS  = (long long)BATCH * SEQ * DIMD;   // 2,097,152
    const long long ATTN_ELEMS = (long long)BATCH * SEQ * SEQ;    // 67,108,864
    float* ctx_out  = out;
    float* attn_out = out + CTX_ELEMS;
    int has_attn = ((long long)out_size >= CTX_ELEMS + ATTN_ELEMS) ? 1 : 0;

    cudaFuncSetAttribute(attn_kernel, cudaFuncAttributeMaxDynamicSharedMemorySize, SM_BYTES);
    attn_kernel<<<BATCH * (SEQ / QT), 256, SM_BYTES>>>(q, k, v, ctx_out, attn_out, has_attn);
}